// round 12
// baseline (speedup 1.0000x reference)
#include <cuda_runtime.h>
#include <cstdint>

// Problem constants
#define BATCH   32
#define PLEN    1024
#define DIM     8
#define SIGLEN  4680        // 8 + 64 + 512 + 4096
#define LVL2_OFF 8
#define LVL3_OFF 72
#define LVL4_OFF 584
#define GROUPS   4          // groups per batch; each group = 8 chunks of 32 incs

// Dynamic smem layout (bytes)
#define S4_BYTES   (8 * 2048 * 8)            // 8 chunks x 2048 u64 (L4)  = 131072
#define SL_OFF     (S4_BYTES)                // L1..L3 per chunk: 8 x 584 floats
#define SL_BYTES   (8 * 584 * 4)             // 18688
#define SX_OFF     (SL_OFF + SL_BYTES)       // increments: 2048 floats
#define SX_BYTES   (2048 * 4)                // 8192
#define SMEM_TOTAL_BYTES (SX_OFF + SX_BYTES) // 157952

// Scratch (device globals — no cudaMalloc allowed)
__device__ float g_buf1[BATCH * GROUPS * SIGLEN];   // group partial sigs (g=1..3 used)
__device__ int   g_flags[BATCH];                    // zero-init; reset by leader

typedef unsigned long long u64;

// ---- packed f32x2 helpers -------------------------------------------------
__device__ __forceinline__ u64 fma2(u64 a, u64 b, u64 c)
{
    u64 d;
    asm("fma.rn.f32x2 %0, %1, %2, %3;" : "=l"(d) : "l"(a), "l"(b), "l"(c));
    return d;
}
__device__ __forceinline__ u64 dup2(float x)
{
    u64 d;
    asm("mov.b64 %0, {%1, %1};" : "=l"(d) : "f"(x));
    return d;
}
__device__ __forceinline__ float2 unpack2(u64 v)
{
    float2 f;
    asm("mov.b64 {%0, %1}, %2;" : "=f"(f.x), "=f"(f.y) : "l"(v));
    return f;
}

// ---------------------------------------------------------------------------
// Single persistent kernel, 1024 threads/block (32 warps/SM).
// Phase 1: 8 chunk signatures per block; each (p,q) row is split between TWO
//          threads (rh = 0/1), each owning 4 r's x 8 s = 32 L4 entries
//          (16 u64). Halved register state doubles resident warps.
// Phase 2: barrier-free in-block Chen reduction on threads t<512 (proven
//          round-11 code); threads t>=512 retire after the phase-1 barrier.
// Phase 3: blocks g=1..3 publish partials; the g=0 leader block spins, then
//          right-multiplies the 3 partials and writes the final output.
//          Grid = 128 blocks, all co-resident -> handoff cannot deadlock.
// ---------------------------------------------------------------------------
__global__ __launch_bounds__(1024) void sig_onekernel(
    const float* __restrict__ path, float* __restrict__ partials,
    int* __restrict__ flags, float* __restrict__ out)
{
    extern __shared__ __align__(16) char smem[];
    u64*   s4 = reinterpret_cast<u64*>(smem);
    float* sL = reinterpret_cast<float*>(smem + SL_OFF);
    float* sx = reinterpret_cast<float*>(smem + SX_OFF);

    const int bx = blockIdx.x;
    const int b  = bx >> 2;
    const int g  = bx & 3;
    const int t  = threadIdx.x;
    const int pq = t & 63;          // (p,q) row within chunk
    const int sc = (t >> 6) & 7;    // chunk within group (0..7)
    const int rh = t >> 9;          // r-half: 0 -> r 0..3, 1 -> r 4..7
    const int p  = pq >> 3;
    const int q  = pq & 7;

    const float* pb = path + (size_t)b * (PLEN * DIM);

    // ---- load this group's 256 increments (vectorized: 2 LDG.128/thread) ----
    if (t < 512) {
        const float4* pb4 = reinterpret_cast<const float4*>(pb);
        int j = t;                       // one float4 per thread (512 total)
        int i = g * 256 + (j >> 1);      // increment index
        int half = j & 1;                // which 4 dims
        float4 v = make_float4(0.f, 0.f, 0.f, 0.f);
        if (i < PLEN - 1) {
            float4 hi = pb4[(i + 1) * 2 + half];
            float4 lo = pb4[i * 2 + half];
            v = make_float4(hi.x - lo.x, hi.y - lo.y, hi.z - lo.z, hi.w - lo.w);
        }
        reinterpret_cast<float4*>(sx)[j] = v;
    }
    __syncthreads();

    const float* sxc = sx + sc * 256;

    // ---- phase 1: 32 L4 entries per thread (4 r's x 8 s) ----
    u64 P[16];          // P[r'*4 + j]: r' 0..3 (r = rh*4+r'), j = s-pair 0..3
    #pragma unroll
    for (int i = 0; i < 16; ++i) P[i] = 0ull;
    u64 A3[2] = {0ull, 0ull};   // a3 r-pairs: (rh*4+0, +1), (rh*4+2, +3)
    float a2 = 0.f, a1p = 0.f;

    #pragma unroll 1
    for (int k = 0; k < 32; ++k) {
        ulonglong2 Xr = *reinterpret_cast<const ulonglong2*>(sxc + k * 8 + rh * 4);
        float xp = sxc[k * 8 + p];
        float xq = sxc[k * 8 + q];

        // shared scalar chain (OLD state)
        float v      = fmaf(xp, (1.0f/24.0f), a1p * (1.0f/6.0f));
        float inner  = fmaf(xq, v, a2 * 0.5f);
        float w      = fmaf(xp, (1.0f/6.0f), a1p * 0.5f);
        float innerW = fmaf(xq, w, a2);
        a2  = fmaf(xq, fmaf(xp, 0.5f, a1p), a2);
        a1p += xp;

        u64 inner2  = dup2(inner);
        u64 innerW2 = dup2(innerW);

        // t4 r-pairs from OLD a3, then a3 update
        u64 T40 = fma2(Xr.x, inner2, A3[0]);
        u64 T41 = fma2(Xr.y, inner2, A3[1]);
        A3[0] = fma2(Xr.x, innerW2, A3[0]);
        A3[1] = fma2(Xr.y, innerW2, A3[1]);

        float2 t01 = unpack2(T40);
        float2 t23 = unpack2(T41);
        u64 d0 = dup2(t01.x);
        u64 d1 = dup2(t01.y);
        u64 d2 = dup2(t23.x);
        u64 d3 = dup2(t23.y);

        #pragma unroll
        for (int jj = 0; jj < 2; ++jj) {
            ulonglong2 xj = *reinterpret_cast<const ulonglong2*>(sxc + k * 8 + 4 * jj);
            P[0  + 2*jj]     = fma2(xj.x, d0, P[0  + 2*jj]);
            P[0  + 2*jj + 1] = fma2(xj.y, d0, P[0  + 2*jj + 1]);
            P[4  + 2*jj]     = fma2(xj.x, d1, P[4  + 2*jj]);
            P[4  + 2*jj + 1] = fma2(xj.y, d1, P[4  + 2*jj + 1]);
            P[8  + 2*jj]     = fma2(xj.x, d2, P[8  + 2*jj]);
            P[8  + 2*jj + 1] = fma2(xj.y, d2, P[8  + 2*jj + 1]);
            P[12 + 2*jj]     = fma2(xj.x, d3, P[12 + 2*jj]);
            P[12 + 2*jj + 1] = fma2(xj.y, d3, P[12 + 2*jj + 1]);
        }
    }

    // ---- store chunk signature into smem ----
    float* L = sL + sc * 584;
    if (rh == 0 && pq < 8) {
        int c  = g * 8 + sc;
        int i0 = c * 32;
        int i1 = min(i0 + 32, PLEN - 1);
        L[pq] = pb[i1 * 8 + pq] - pb[i0 * 8 + pq];   // telescoped level-1
    }
    if (rh == 0) L[LVL2_OFF + pq] = a2;
    #pragma unroll
    for (int rp = 0; rp < 2; ++rp) {
        float2 a3v = unpack2(A3[rp]);
        L[LVL3_OFF + pq * 8 + rh * 4 + 2 * rp]     = a3v.x;
        L[LVL3_OFF + pq * 8 + rh * 4 + 2 * rp + 1] = a3v.y;
    }
    {
        u64* s4c = s4 + sc * 2048 + pq * 32;
        int sw = pq & 31;
        #pragma unroll
        for (int i = 0; i < 16; ++i) s4c[(rh * 16 + i) ^ sw] = P[i];
    }
    __syncthreads();

    if (t >= 512) return;   // upper half retires; phases 2-3 run on 512 threads

    // ---- phase 2: barrier-free Chen reduction of 8 chunk sigs ----
    const int p2  = t >> 6;
    const int q2  = (t >> 3) & 7;
    const int r2  = t & 7;
    const int pq2 = t >> 3;
    const int qr2 = t & 63;
    const int swr = pq2 & 31;

    float c4[8];
    {
        const u64* bc = s4 + pq2 * 32;   // chunk 0
        #pragma unroll
        for (int j = 0; j < 4; ++j) {
            float2 vv = unpack2(bc[(r2 * 4 + j) ^ swr]);
            c4[2 * j]     = vv.x;
            c4[2 * j + 1] = vv.y;
        }
    }
    float c3  = sL[LVL3_OFF + t];
    float a2r = sL[LVL2_OFF + pq2];
    float a1r = sL[p2];

    // prefetch chunk 1's transposed L4 slice
    u64 nb[4];
    {
        const u64* bc = s4 + 2048 + pq2 * 32;
        #pragma unroll
        for (int j = 0; j < 4; ++j) nb[j] = bc[(r2 * 4 + j) ^ swr];
    }

    #pragma unroll 1
    for (int i = 1; i < 8; ++i) {
        float b4[8];
        #pragma unroll
        for (int j = 0; j < 4; ++j) {
            float2 vv = unpack2(nb[j]);
            b4[2 * j]     = vv.x;
            b4[2 * j + 1] = vv.y;
        }
        if (i + 1 < 8) {
            const u64* bc = s4 + (i + 1) * 2048 + pq2 * 32;
            #pragma unroll
            for (int j = 0; j < 4; ++j) nb[j] = bc[(r2 * 4 + j) ^ swr];
        }

        const float* B = sL + i * 584;

        const float4* b3s = reinterpret_cast<const float4*>(B + LVL3_OFF + qr2 * 8);
        const float4* b2s = reinterpret_cast<const float4*>(B + LVL2_OFF + r2 * 8);
        const float4* b1s = reinterpret_cast<const float4*>(B);
        float4 w3a = b3s[0], w3b = b3s[1];
        float4 w2a = b2s[0], w2b = b2s[1];
        float4 w1a = b1s[0], w1b = b1s[1];
        float b3a[8] = {w3a.x,w3a.y,w3a.z,w3a.w,w3b.x,w3b.y,w3b.z,w3b.w};
        float b2a[8] = {w2a.x,w2a.y,w2a.z,w2a.w,w2b.x,w2b.y,w2b.z,w2b.w};
        float b1a[8] = {w1a.x,w1a.y,w1a.z,w1a.w,w1b.x,w1b.y,w1b.z,w1b.w};

        #pragma unroll
        for (int s = 0; s < 8; ++s) {
            float cc = c4[s] + b4[s];
            cc = fmaf(a1r, b3a[s], cc);
            cc = fmaf(a2r, b2a[s], cc);
            cc = fmaf(c3,  b1a[s], cc);   // OLD c3
            c4[s] = cc;
        }

        float b3t  = B[LVL3_OFF + t];
        float b2qr = B[LVL2_OFF + qr2];
        float b2pq = B[LVL2_OFF + pq2];
        float b1r  = B[r2];
        float b1q  = B[q2];
        float b1p  = B[p2];

        float nc3 = c3 + b3t + a1r * b2qr + a2r * b1r;   // old a1, a2
        float na2 = a2r + b2pq + a1r * b1q;              // old a1
        float na1 = a1r + b1p;
        c3 = nc3; a2r = na2; a1r = na1;
    }

    // ---- phase 3: handoff ----
    if (g != 0) {
        // publish group partial, arrive on flag, exit
        float* O = partials + (size_t)bx * SIGLEN;
        if ((t & 63) == 0) O[p2] = a1r;
        if (r2 == 0)       O[LVL2_OFF + pq2] = a2r;
        O[LVL3_OFF + t] = c3;
        float4* O4 = reinterpret_cast<float4*>(O + LVL4_OFF);
        O4[2 * t]     = make_float4(c4[0], c4[1], c4[2], c4[3]);
        O4[2 * t + 1] = make_float4(c4[4], c4[5], c4[6], c4[7]);
        __threadfence();
        __syncthreads();
        if (t == 0) atomicAdd(&flags[b], 1);
        return;
    }

    // leader: wait for the 3 sibling groups
    if (t == 0) {
        while (atomicAdd(&flags[b], 0) < 3) __nanosleep(32);
        flags[b] = 0;            // reset for next replay
        __threadfence();
    }
    __syncthreads();

    // stage the 3 partials' levels 1..3 into smem (float4, reuse sL) and
    // prefetch ALL 3 partials' L4 slices into registers (MLP = 3)
    const float* PS = partials + (size_t)(b * GROUPS) * SIGLEN;
    float4 plo[3], phi[3];
    #pragma unroll
    for (int j = 0; j < 3; ++j) {
        const float4* B4 = reinterpret_cast<const float4*>(
            PS + (size_t)(j + 1) * SIGLEN + LVL4_OFF);
        plo[j] = __ldcg(B4 + 2 * t);
        phi[j] = __ldcg(B4 + 2 * t + 1);
    }
    if (t < 146) {
        #pragma unroll
        for (int j = 1; j < GROUPS; ++j) {
            const float4* Bp4 = reinterpret_cast<const float4*>(
                PS + (size_t)j * SIGLEN);
            reinterpret_cast<float4*>(sL)[(j - 1) * 146 + t] = __ldcg(Bp4 + t);
        }
    }
    __syncthreads();

    #pragma unroll
    for (int i = 0; i < 3; ++i) {
        float b4[8] = {plo[i].x, plo[i].y, plo[i].z, plo[i].w,
                       phi[i].x, phi[i].y, phi[i].z, phi[i].w};
        const float* B = sL + i * 584;

        const float4* b3s = reinterpret_cast<const float4*>(B + LVL3_OFF + qr2 * 8);
        const float4* b2s = reinterpret_cast<const float4*>(B + LVL2_OFF + r2 * 8);
        const float4* b1s = reinterpret_cast<const float4*>(B);
        float4 w3a = b3s[0], w3b = b3s[1];
        float4 w2a = b2s[0], w2b = b2s[1];
        float4 w1a = b1s[0], w1b = b1s[1];
        float b3a[8] = {w3a.x,w3a.y,w3a.z,w3a.w,w3b.x,w3b.y,w3b.z,w3b.w};
        float b2a[8] = {w2a.x,w2a.y,w2a.z,w2a.w,w2b.x,w2b.y,w2b.z,w2b.w};
        float b1a[8] = {w1a.x,w1a.y,w1a.z,w1a.w,w1b.x,w1b.y,w1b.z,w1b.w};

        #pragma unroll
        for (int s = 0; s < 8; ++s) {
            float cc = c4[s] + b4[s];
            cc = fmaf(a1r, b3a[s], cc);
            cc = fmaf(a2r, b2a[s], cc);
            cc = fmaf(c3,  b1a[s], cc);   // OLD c3
            c4[s] = cc;
        }

        float b3t  = B[LVL3_OFF + t];
        float b2qr = B[LVL2_OFF + qr2];
        float b2pq = B[LVL2_OFF + pq2];
        float b1r  = B[r2];
        float b1q  = B[q2];
        float b1p  = B[p2];

        float nc3 = c3 + b3t + a1r * b2qr + a2r * b1r;
        float na2 = a2r + b2pq + a1r * b1q;
        float na1 = a1r + b1p;
        c3 = nc3; a2r = na2; a1r = na1;
    }

    // final output layout: [L1 32x8][L2 32x64][L3 32x512][L4 32x4096]
    float* o1 = out + (size_t)b * 8;
    float* o2 = out + 256   + (size_t)b * 64;
    float* o3 = out + 2304  + (size_t)b * 512;
    float* o4 = out + 18688 + (size_t)b * 4096;
    if ((t & 63) == 0) o1[p2] = a1r;
    if (r2 == 0)       o2[pq2] = a2r;
    o3[t] = c3;
    float4* O4 = reinterpret_cast<float4*>(o4);
    O4[2 * t]     = make_float4(c4[0], c4[1], c4[2], c4[3]);
    O4[2 * t + 1] = make_float4(c4[4], c4[5], c4[6], c4[7]);
}

// ---------------------------------------------------------------------------
extern "C" void kernel_launch(void* const* d_in, const int* in_sizes, int n_in,
                              void* d_out, int out_size)
{
    const float* path = (const float*)d_in[0];
    float* out = (float*)d_out;

    float* buf1;
    int* flags;
    cudaGetSymbolAddress((void**)&buf1, g_buf1);
    cudaGetSymbolAddress((void**)&flags, g_flags);

    cudaFuncSetAttribute(sig_onekernel,
                         cudaFuncAttributeMaxDynamicSharedMemorySize,
                         SMEM_TOTAL_BYTES);

    // single launch: chunk sigs + in-block reduce + in-grid final handoff
    sig_onekernel<<<BATCH * GROUPS, 1024, SMEM_TOTAL_BYTES>>>(path, buf1, flags, out);
}

// round 13
// speedup vs baseline: 1.1756x; 1.1756x over previous
#include <cuda_runtime.h>
#include <cstdint>

// Problem constants
#define BATCH   32
#define PLEN    1024
#define DIM     8
#define SIGLEN  4680        // 8 + 64 + 512 + 4096
#define LVL2_OFF 8
#define LVL3_OFF 72
#define LVL4_OFF 584
#define GROUPS   4          // groups per batch; each group = 8 chunks of 32 incs

// Dynamic smem layout (bytes)
#define S4_BYTES   (8 * 2048 * 8)            // 8 chunks x 2048 u64 (L4)  = 131072
#define SL_OFF     (S4_BYTES)                // L1..L3 per chunk: 8 x 584 floats
#define SL_BYTES   (8 * 584 * 4)             // 18688
#define SX_OFF     (SL_OFF + SL_BYTES)       // increments: 2048 floats
#define SX_BYTES   (2048 * 4)                // 8192
#define SMEM_TOTAL_BYTES (SX_OFF + SX_BYTES) // 157952

// Scratch (device globals — no cudaMalloc allowed)
__device__ float g_buf1[BATCH * GROUPS * SIGLEN];   // group partial sigs (g=1..3 used)
__device__ int   g_flags[BATCH];                    // zero-init; reset by leader

typedef unsigned long long u64;

// ---- packed f32x2 helpers -------------------------------------------------
__device__ __forceinline__ u64 fma2(u64 a, u64 b, u64 c)
{
    u64 d;
    asm("fma.rn.f32x2 %0, %1, %2, %3;" : "=l"(d) : "l"(a), "l"(b), "l"(c));
    return d;
}
__device__ __forceinline__ u64 dup2(float x)
{
    u64 d;
    asm("mov.b64 %0, {%1, %1};" : "=l"(d) : "f"(x));
    return d;
}
__device__ __forceinline__ float2 unpack2(u64 v)
{
    float2 f;
    asm("mov.b64 {%0, %1}, %2;" : "=f"(f.x), "=f"(f.y) : "l"(v));
    return f;
}

// ---------------------------------------------------------------------------
// Single persistent kernel (round-11 structure, unroll-4 phase 1).
// Phase 1: 8 chunk signatures per block (32 increments each), one (p,q) row
//          (64 level-4 entries) per thread, s-pair f32x2 packing.
// Phase 2: barrier-free in-block Chen reduction of the 8 chunk sigs, with
//          register double-buffering of the transposed L4 reads.
// Phase 3: blocks g=1..3 publish partials; the g=0 leader block spins, then
//          right-multiplies the 3 partials (front-batched loads, MLP=9) and
//          writes the final output. Grid = 128 blocks, all co-resident ->
//          handoff cannot deadlock.
// ---------------------------------------------------------------------------
__global__ __launch_bounds__(512) void sig_onekernel(
    const float* __restrict__ path, float* __restrict__ partials,
    int* __restrict__ flags, float* __restrict__ out)
{
    extern __shared__ __align__(16) char smem[];
    u64*   s4 = reinterpret_cast<u64*>(smem);
    float* sL = reinterpret_cast<float*>(smem + SL_OFF);
    float* sx = reinterpret_cast<float*>(smem + SX_OFF);

    const int bx = blockIdx.x;
    const int b  = bx >> 2;
    const int g  = bx & 3;
    const int t  = threadIdx.x;
    const int sc  = t >> 6;      // chunk within group (0..7)
    const int tpq = t & 63;      // (p,q) row within chunk
    const int p   = tpq >> 3;
    const int q   = tpq & 7;

    const float* pb = path + (size_t)b * (PLEN * DIM);

    // ---- load this group's 256 increments (vectorized: 2 LDG.128/thread) ----
    {
        const float4* pb4 = reinterpret_cast<const float4*>(pb);
        int j = t;                       // one float4 per thread (512 total)
        int i = g * 256 + (j >> 1);      // increment index
        int half = j & 1;                // which 4 dims
        float4 v = make_float4(0.f, 0.f, 0.f, 0.f);
        if (i < PLEN - 1) {
            float4 hi = pb4[(i + 1) * 2 + half];
            float4 lo = pb4[i * 2 + half];
            v = make_float4(hi.x - lo.x, hi.y - lo.y, hi.z - lo.z, hi.w - lo.w);
        }
        reinterpret_cast<float4*>(sx)[j] = v;
    }
    __syncthreads();

    const float* sxc = sx + sc * 256;

    // ---- phase 1: chunk signature, 64 L4 entries per thread ----
    u64 P[32];          // a4[r][s-pair j], idx = r*4+j
    #pragma unroll
    for (int i = 0; i < 32; ++i) P[i] = 0ull;
    u64 A3[4] = {0ull, 0ull, 0ull, 0ull};  // a3 pairs (2rp,2rp+1)
    float a2 = 0.f, a1p = 0.f;

    #pragma unroll 4
    for (int k = 0; k < 32; ++k) {
        ulonglong2 xa = *reinterpret_cast<const ulonglong2*>(sxc + k * 8);
        ulonglong2 xb = *reinterpret_cast<const ulonglong2*>(sxc + k * 8 + 4);
        u64 Xv[4] = {xa.x, xa.y, xb.x, xb.y};
        float xp = sxc[k * 8 + p];
        float xq = sxc[k * 8 + q];

        // shared scalar chain (OLD state)
        float v      = fmaf(xp, (1.0f/24.0f), a1p * (1.0f/6.0f));
        float inner  = fmaf(xq, v, a2 * 0.5f);
        float w      = fmaf(xp, (1.0f/6.0f), a1p * 0.5f);
        float innerW = fmaf(xq, w, a2);
        a2  = fmaf(xq, fmaf(xp, 0.5f, a1p), a2);
        a1p += xp;

        u64 inner2  = dup2(inner);
        u64 innerW2 = dup2(innerW);

        #pragma unroll
        for (int rp = 0; rp < 4; ++rp) {
            u64 t4p = fma2(Xv[rp], inner2, A3[rp]);   // OLD a3 pair
            A3[rp]  = fma2(Xv[rp], innerW2, A3[rp]);
            float2 tt = unpack2(t4p);
            u64 tlo = dup2(tt.x);
            u64 thi = dup2(tt.y);
            #pragma unroll
            for (int j = 0; j < 4; ++j)
                P[(2 * rp) * 4 + j] = fma2(Xv[j], tlo, P[(2 * rp) * 4 + j]);
            #pragma unroll
            for (int j = 0; j < 4; ++j)
                P[(2 * rp + 1) * 4 + j] = fma2(Xv[j], thi, P[(2 * rp + 1) * 4 + j]);
        }
    }

    // ---- store chunk signature into smem ----
    float* L = sL + sc * 584;
    if (tpq < 8) {
        int c  = g * 8 + sc;
        int i0 = c * 32;
        int i1 = min(i0 + 32, PLEN - 1);
        L[tpq] = pb[i1 * 8 + tpq] - pb[i0 * 8 + tpq];   // telescoped level-1
    }
    L[LVL2_OFF + tpq] = a2;
    #pragma unroll
    for (int rp = 0; rp < 4; ++rp) {
        float2 a3v = unpack2(A3[rp]);
        L[LVL3_OFF + tpq * 8 + 2 * rp]     = a3v.x;
        L[LVL3_OFF + tpq * 8 + 2 * rp + 1] = a3v.y;
    }
    {
        u64* s4c = s4 + sc * 2048 + tpq * 32;
        int sw = tpq & 31;
        #pragma unroll
        for (int idx = 0; idx < 32; ++idx) s4c[idx ^ sw] = P[idx];
    }
    __syncthreads();

    // ---- phase 2: barrier-free Chen reduction of 8 chunk sigs ----
    const int p2  = t >> 6;
    const int q2  = (t >> 3) & 7;
    const int r2  = t & 7;
    const int pq2 = t >> 3;
    const int qr2 = t & 63;
    const int swr = pq2 & 31;

    float c4[8];
    {
        const u64* bc = s4 + pq2 * 32;   // chunk 0
        #pragma unroll
        for (int j = 0; j < 4; ++j) {
            float2 vv = unpack2(bc[(r2 * 4 + j) ^ swr]);
            c4[2 * j]     = vv.x;
            c4[2 * j + 1] = vv.y;
        }
    }
    float c3  = sL[LVL3_OFF + t];
    float a2r = sL[LVL2_OFF + pq2];
    float a1r = sL[p2];

    // prefetch chunk 1's transposed L4 slice
    u64 nb[4];
    {
        const u64* bc = s4 + 2048 + pq2 * 32;
        #pragma unroll
        for (int j = 0; j < 4; ++j) nb[j] = bc[(r2 * 4 + j) ^ swr];
    }

    #pragma unroll 1
    for (int i = 1; i < 8; ++i) {
        float b4[8];
        #pragma unroll
        for (int j = 0; j < 4; ++j) {
            float2 vv = unpack2(nb[j]);
            b4[2 * j]     = vv.x;
            b4[2 * j + 1] = vv.y;
        }
        if (i + 1 < 8) {
            const u64* bc = s4 + (i + 1) * 2048 + pq2 * 32;
            #pragma unroll
            for (int j = 0; j < 4; ++j) nb[j] = bc[(r2 * 4 + j) ^ swr];
        }

        const float* B = sL + i * 584;

        const float4* b3s = reinterpret_cast<const float4*>(B + LVL3_OFF + qr2 * 8);
        const float4* b2s = reinterpret_cast<const float4*>(B + LVL2_OFF + r2 * 8);
        const float4* b1s = reinterpret_cast<const float4*>(B);
        float4 w3a = b3s[0], w3b = b3s[1];
        float4 w2a = b2s[0], w2b = b2s[1];
        float4 w1a = b1s[0], w1b = b1s[1];
        float b3a[8] = {w3a.x,w3a.y,w3a.z,w3a.w,w3b.x,w3b.y,w3b.z,w3b.w};
        float b2a[8] = {w2a.x,w2a.y,w2a.z,w2a.w,w2b.x,w2b.y,w2b.z,w2b.w};
        float b1a[8] = {w1a.x,w1a.y,w1a.z,w1a.w,w1b.x,w1b.y,w1b.z,w1b.w};

        #pragma unroll
        for (int s = 0; s < 8; ++s) {
            float cc = c4[s] + b4[s];
            cc = fmaf(a1r, b3a[s], cc);
            cc = fmaf(a2r, b2a[s], cc);
            cc = fmaf(c3,  b1a[s], cc);   // OLD c3
            c4[s] = cc;
        }

        float b3t  = B[LVL3_OFF + t];
        float b2qr = B[LVL2_OFF + qr2];
        float b2pq = B[LVL2_OFF + pq2];
        float b1r  = B[r2];
        float b1q  = B[q2];
        float b1p  = B[p2];

        float nc3 = c3 + b3t + a1r * b2qr + a2r * b1r;   // old a1, a2
        float na2 = a2r + b2pq + a1r * b1q;              // old a1
        float na1 = a1r + b1p;
        c3 = nc3; a2r = na2; a1r = na1;
    }

    // ---- phase 3: handoff ----
    if (g != 0) {
        // publish group partial, arrive on flag, exit
        float* O = partials + (size_t)bx * SIGLEN;
        if ((t & 63) == 0) O[p2] = a1r;
        if (r2 == 0)       O[LVL2_OFF + pq2] = a2r;
        O[LVL3_OFF + t] = c3;
        float4* O4 = reinterpret_cast<float4*>(O + LVL4_OFF);
        O4[2 * t]     = make_float4(c4[0], c4[1], c4[2], c4[3]);
        O4[2 * t + 1] = make_float4(c4[4], c4[5], c4[6], c4[7]);
        __threadfence();
        __syncthreads();
        if (t == 0) atomicAdd(&flags[b], 1);
        return;
    }

    // leader: wait for the 3 sibling groups
    if (t == 0) {
        while (atomicAdd(&flags[b], 0) < 3) __nanosleep(32);
        flags[b] = 0;            // reset for next replay
        __threadfence();
    }
    __syncthreads();

    // front-batch ALL partial loads (MLP = 9): smem staging of levels 1..3
    // first (consumed first after the barrier), then the 3 L4 slices.
    const float* PS = partials + (size_t)(b * GROUPS) * SIGLEN;
    if (t < 146) {
        #pragma unroll
        for (int j = 1; j < GROUPS; ++j) {
            const float4* Bp4 = reinterpret_cast<const float4*>(
                PS + (size_t)j * SIGLEN);
            reinterpret_cast<float4*>(sL)[(j - 1) * 146 + t] = __ldcg(Bp4 + t);
        }
    }
    float4 plo[3], phi[3];
    #pragma unroll
    for (int j = 0; j < 3; ++j) {
        const float4* B4 = reinterpret_cast<const float4*>(
            PS + (size_t)(j + 1) * SIGLEN + LVL4_OFF);
        plo[j] = __ldcg(B4 + 2 * t);
        phi[j] = __ldcg(B4 + 2 * t + 1);
    }
    __syncthreads();

    #pragma unroll
    for (int i = 0; i < 3; ++i) {
        float b4[8] = {plo[i].x, plo[i].y, plo[i].z, plo[i].w,
                       phi[i].x, phi[i].y, phi[i].z, phi[i].w};
        const float* B = sL + i * 584;

        const float4* b3s = reinterpret_cast<const float4*>(B + LVL3_OFF + qr2 * 8);
        const float4* b2s = reinterpret_cast<const float4*>(B + LVL2_OFF + r2 * 8);
        const float4* b1s = reinterpret_cast<const float4*>(B);
        float4 w3a = b3s[0], w3b = b3s[1];
        float4 w2a = b2s[0], w2b = b2s[1];
        float4 w1a = b1s[0], w1b = b1s[1];
        float b3a[8] = {w3a.x,w3a.y,w3a.z,w3a.w,w3b.x,w3b.y,w3b.z,w3b.w};
        float b2a[8] = {w2a.x,w2a.y,w2a.z,w2a.w,w2b.x,w2b.y,w2b.z,w2b.w};
        float b1a[8] = {w1a.x,w1a.y,w1a.z,w1a.w,w1b.x,w1b.y,w1b.z,w1b.w};

        #pragma unroll
        for (int s = 0; s < 8; ++s) {
            float cc = c4[s] + b4[s];
            cc = fmaf(a1r, b3a[s], cc);
            cc = fmaf(a2r, b2a[s], cc);
            cc = fmaf(c3,  b1a[s], cc);   // OLD c3
            c4[s] = cc;
        }

        float b3t  = B[LVL3_OFF + t];
        float b2qr = B[LVL2_OFF + qr2];
        float b2pq = B[LVL2_OFF + pq2];
        float b1r  = B[r2];
        float b1q  = B[q2];
        float b1p  = B[p2];

        float nc3 = c3 + b3t + a1r * b2qr + a2r * b1r;
        float na2 = a2r + b2pq + a1r * b1q;
        float na1 = a1r + b1p;
        c3 = nc3; a2r = na2; a1r = na1;
    }

    // final output layout: [L1 32x8][L2 32x64][L3 32x512][L4 32x4096]
    float* o1 = out + (size_t)b * 8;
    float* o2 = out + 256   + (size_t)b * 64;
    float* o3 = out + 2304  + (size_t)b * 512;
    float* o4 = out + 18688 + (size_t)b * 4096;
    if ((t & 63) == 0) o1[p2] = a1r;
    if (r2 == 0)       o2[pq2] = a2r;
    o3[t] = c3;
    float4* O4 = reinterpret_cast<float4*>(o4);
    O4[2 * t]     = make_float4(c4[0], c4[1], c4[2], c4[3]);
    O4[2 * t + 1] = make_float4(c4[4], c4[5], c4[6], c4[7]);
}

// ---------------------------------------------------------------------------
extern "C" void kernel_launch(void* const* d_in, const int* in_sizes, int n_in,
                              void* d_out, int out_size)
{
    const float* path = (const float*)d_in[0];
    float* out = (float*)d_out;

    float* buf1;
    int* flags;
    cudaGetSymbolAddress((void**)&buf1, g_buf1);
    cudaGetSymbolAddress((void**)&flags, g_flags);

    cudaFuncSetAttribute(sig_onekernel,
                         cudaFuncAttributeMaxDynamicSharedMemorySize,
                         SMEM_TOTAL_BYTES);

    // single launch: chunk sigs + in-block reduce + in-grid final handoff
    sig_onekernel<<<BATCH * GROUPS, 512, SMEM_TOTAL_BYTES>>>(path, buf1, flags, out);
}